// round 7
// baseline (speedup 1.0000x reference)
#include <cuda_runtime.h>
#include <math.h>
#include <limits.h>

// L2loss over bucketized histograms — analytic segment version, SINGLE BLOCK.
// h(p) per channel is a step function whose breakpoints are the cum values.
// Sum_p (h1-h2)^2 = sum over segments [x, next(x)) of len * d^2, candidates =
// the 6*256 cum values + sentinel 0, deduped at first occurrence.
// One block of 512 threads handles all 1537 candidates (grid-stride loop),
// so there are NO global atomics, no ticket, no device-global state at all.

namespace {
constexpr int KBINS = 256;
constexpr int NPIX  = 224 * 224;       // 50176
constexpr int TPB   = 512;             // 16 warps
constexpr int NENT  = 6 * KBINS + 1;   // 1537 candidate breakpoints
constexpr int NWARP = TPB / 32;        // 16
}

__global__ void __launch_bounds__(TPB)
l2hist_kernel(const float* __restrict__ target,
              const float* __restrict__ output,
              float* __restrict__ out)
{
    __shared__ alignas(16) int s_cum[6][KBINS];
    __shared__ unsigned int    s_wred[NWARP][3];

    const int tid  = threadIdx.x;
    const int lane = tid & 31;
    const int warp = tid >> 5;

    // ---- Scan: warps 0..5 compute floor(cumsum) of their array. ----
    if (warp < 6) {
        const float* src = (warp < 3) ? target + (warp << 8)
                                      : output + ((warp - 3) << 8);
        const float4 v0 = __ldg((const float4*)(src + (lane << 3)));
        const float4 v1 = __ldg((const float4*)(src + (lane << 3) + 4));

        float q0 = v0.x;
        float q1 = q0 + v0.y;
        float q2 = q1 + v0.z;
        float q3 = q2 + v0.w;
        float q4 = q3 + v1.x;
        float q5 = q4 + v1.y;
        float q6 = q5 + v1.z;
        float q7 = q6 + v1.w;          // lane total

        float inc = q7;                // inclusive scan of lane totals
        #pragma unroll
        for (int off = 1; off < 32; off <<= 1) {
            const float n = __shfl_up_sync(0xFFFFFFFFu, inc, off);
            if (lane >= off) inc += n;
        }
        float excl = __shfl_up_sync(0xFFFFFFFFu, inc, 1);
        if (lane == 0) excl = 0.0f;

        int4 w0, w1;
        w0.x = __float2int_rd(excl + q0);
        w0.y = __float2int_rd(excl + q1);
        w0.z = __float2int_rd(excl + q2);
        w0.w = __float2int_rd(excl + q3);
        w1.x = __float2int_rd(excl + q4);
        w1.y = __float2int_rd(excl + q5);
        w1.z = __float2int_rd(excl + q6);
        w1.w = __float2int_rd(excl + q7);
        *(int4*)&s_cum[warp][(lane << 3)]     = w0;
        *(int4*)&s_cum[warp][(lane << 3) + 4] = w1;
    }
    __syncthreads();

    unsigned int acc[3] = {0u, 0u, 0u};

    // ---- Each thread evaluates candidates tid, tid+512, tid+1024 (+1536). ----
    for (int gid = tid; gid < NENT; gid += TPB) {
        // Breakpoint value x: gid 0 is the sentinel x=0; otherwise entry
        // e = gid-1 maps to array a_src = e>>8, index j_src = e&255.
        int a_src = -1, j_src = 0, x = 0;
        if (gid != 0) {
            const int e = gid - 1;
            a_src = e >> 8;
            j_src = e & (KBINS - 1);
            x = s_cum[a_src][j_src];
        }

        // Saturating searches: s[a] = min(count(cum[a] <= x), 255).
        int s[6];
        #pragma unroll
        for (int a = 0; a < 6; ++a) s[a] = 0;
        #pragma unroll
        for (int w = 128; w; w >>= 1) {
            #pragma unroll
            for (int a = 0; a < 6; ++a)
                if (s_cum[a][s[a] + w - 1] <= x) s[a] += w;
        }

        // Exact counts, presence of x, and next breakpoint > x.
        int  cnt[6];
        bool pres[6];
        int  nxt = NPIX;
        #pragma unroll
        for (int a = 0; a < 6; ++a) {
            int c = s[a];
            if (c == KBINS - 1 && s_cum[a][KBINS - 1] <= x) c = KBINS; // 256
            cnt[a]  = c;
            pres[a] = (c > 0) && (s_cum[a][c - 1] == x);
            const int nv = (c < KBINS) ? s_cum[a][c] : INT_MAX;
            nxt = (nv < nxt) ? nv : nxt;
        }
        const int len = (nxt > x) ? (nxt - x) : 0;   // nxt already <= NPIX

        // Dedup: count this segment only at the first occurrence of x.
        bool canonical;
        if (gid == 0) {
            canonical = !(pres[0] || pres[1] || pres[2] ||
                          pres[3] || pres[4] || pres[5]);
        } else {
            canonical = (j_src == 0) || (s_cum[a_src][j_src - 1] < x);
            #pragma unroll
            for (int a = 0; a < 6; ++a)
                if (a < a_src && pres[a]) canonical = false;
        }

        if (canonical && len > 0) {
            // h values at p = x with cross-channel carry.
            int h1 = 0, h2 = 0;
            #pragma unroll
            for (int c = 0; c < 3; ++c) {
                const int c1 = cnt[c], c2 = cnt[c + 3];
                if (c1 <= KBINS - 2)      h1 = c1;
                else if (c1 == KBINS)     h1 = KBINS - 1;   // count was 256
                /* c1 == 255: keep previous channel's value */
                if (c2 <= KBINS - 2)      h2 = c2;
                else if (c2 == KBINS)     h2 = KBINS - 1;
                const int d = h1 - h2;
                // len*d^2 <= 50176*65025 < 2^32; channel totals are sums
                // over disjoint segments tiling [0, NPIX), so fit u32 too.
                acc[c] += (unsigned int)len * (unsigned int)(d * d);
            }
        }
    }

    // ---- Warp reduce, then warp0 reduces the 16 warp partials. ----
    #pragma unroll
    for (int c = 0; c < 3; ++c)
        acc[c] = __reduce_add_sync(0xFFFFFFFFu, acc[c]);
    if (lane == 0) {
        s_wred[warp][0] = acc[0];
        s_wred[warp][1] = acc[1];
        s_wred[warp][2] = acc[2];
    }
    __syncthreads();

    if (warp == 0) {
        unsigned int b0 = (lane < NWARP) ? s_wred[lane][0] : 0u;
        unsigned int b1 = (lane < NWARP) ? s_wred[lane][1] : 0u;
        unsigned int b2 = (lane < NWARP) ? s_wred[lane][2] : 0u;
        b0 = __reduce_add_sync(0xFFFFFFFFu, b0);
        b1 = __reduce_add_sync(0xFFFFFFFFu, b1);
        b2 = __reduce_add_sync(0xFFFFFFFFu, b2);
        if (lane == 0)
            *out = sqrtf((float)b0) + sqrtf((float)b1) + sqrtf((float)b2);
    }
}

extern "C" void kernel_launch(void* const* d_in, const int* in_sizes, int n_in,
                              void* d_out, int out_size)
{
    const float* target = (const float*)d_in[0];  // (3, 256, 1) fp32
    const float* output = (const float*)d_in[1];  // (3, 256, 1) fp32
    float* out = (float*)d_out;                   // scalar fp32
    (void)in_sizes; (void)n_in; (void)out_size;

    l2hist_kernel<<<1, TPB>>>(target, output, out);
}

// round 8
// speedup vs baseline: 1.3023x; 1.3023x over previous
#include <cuda_runtime.h>
#include <math.h>
#include <limits.h>

// L2loss over bucketized histograms — analytic segment version (R8).
// h(p) per channel is a step function with breakpoints at the cum values.
// Sum_p (h1-h2)^2 = sum over segments [x, next(x)) of len*d^2, candidates =
// the 6*256 cum values, deduped at first occurrence. (The p<min(cum) segment
// always contributes 0, so no sentinel entry is needed.)
// 8 blocks x 192 threads = 1536 = one candidate per thread.
// Tail: packed atomics with the block-completion counter fused into the ch2
// accumulator -> last block needs a single global read-back.

namespace {
constexpr int KBINS = 256;
constexpr int NPIX  = 224 * 224;     // 50176
constexpr int TPB   = 192;           // 6 warps (one per scanned array)
constexpr int NENT  = 6 * KBINS;     // 1536 candidate breakpoints
constexpr int NBLK  = NENT / TPB;    // 8
constexpr int NWARP = TPB / 32;      // 6
}

__device__ unsigned long long g_a01;   // ch0 in low 32, ch1 in high 32
__device__ unsigned long long g_a2c;   // ch2 in low 32, block count in high 32

__global__ void __launch_bounds__(TPB)
l2hist_kernel(const float* __restrict__ target,
              const float* __restrict__ output,
              float* __restrict__ out)
{
    __shared__ alignas(16) int s_cum[6][KBINS];
    __shared__ unsigned int    s_wred[NWARP][3];

    const int tid  = threadIdx.x;
    const int lane = tid & 31;
    const int warp = tid >> 5;

    // ---- Scan: warp a computes floor(cumsum) of array a. ----
    // Lane l owns elements [8l, 8l+8): serial in-lane prefix, Kogge-Stone
    // over lane totals, exclusive offset via shfl_up(1).
    {
        const float* src = (warp < 3) ? target + (warp << 8)
                                      : output + ((warp - 3) << 8);
        const float4 v0 = __ldg((const float4*)(src + (lane << 3)));
        const float4 v1 = __ldg((const float4*)(src + (lane << 3) + 4));

        float q0 = v0.x;
        float q1 = q0 + v0.y;
        float q2 = q1 + v0.z;
        float q3 = q2 + v0.w;
        float q4 = q3 + v1.x;
        float q5 = q4 + v1.y;
        float q6 = q5 + v1.z;
        float q7 = q6 + v1.w;          // lane total

        float inc = q7;
        #pragma unroll
        for (int off = 1; off < 32; off <<= 1) {
            const float n = __shfl_up_sync(0xFFFFFFFFu, inc, off);
            if (lane >= off) inc += n;
        }
        float excl = __shfl_up_sync(0xFFFFFFFFu, inc, 1);
        if (lane == 0) excl = 0.0f;

        int4 w0, w1;
        w0.x = __float2int_rd(excl + q0);
        w0.y = __float2int_rd(excl + q1);
        w0.z = __float2int_rd(excl + q2);
        w0.w = __float2int_rd(excl + q3);
        w1.x = __float2int_rd(excl + q4);
        w1.y = __float2int_rd(excl + q5);
        w1.z = __float2int_rd(excl + q6);
        w1.w = __float2int_rd(excl + q7);
        *(int4*)&s_cum[warp][(lane << 3)]     = w0;
        *(int4*)&s_cum[warp][(lane << 3) + 4] = w1;
    }
    __syncthreads();

    // ---- One candidate breakpoint per thread. ----
    const int e     = blockIdx.x * TPB + tid;   // 0..1535, always valid
    const int a_src = e >> 8;
    const int j_src = e & (KBINS - 1);
    const int x     = s_cum[a_src][j_src];

    // Saturating searches: s[a] = min(count(cum[a] <= x), 255).
    int s[6];
    #pragma unroll
    for (int a = 0; a < 6; ++a) s[a] = 0;
    #pragma unroll
    for (int w = 128; w; w >>= 1) {
        #pragma unroll
        for (int a = 0; a < 6; ++a)
            if (s_cum[a][s[a] + w - 1] <= x) s[a] += w;
    }

    // Exact counts, presence of x, next breakpoint > x.
    int  cnt[6];
    bool pres[6];
    int  nxt = NPIX;
    #pragma unroll
    for (int a = 0; a < 6; ++a) {
        int c = s[a];
        if (c == KBINS - 1 && s_cum[a][KBINS - 1] <= x) c = KBINS;  // count 256
        cnt[a]  = c;
        pres[a] = (c > 0) && (s_cum[a][c - 1] == x);
        const int nv = (c < KBINS) ? s_cum[a][c] : INT_MAX;
        nxt = (nv < nxt) ? nv : nxt;
    }
    const int len = (nxt > x) ? (nxt - x) : 0;     // nxt already <= NPIX

    // Dedup: only the first occurrence of value x (array order, then index).
    bool canonical = (j_src == 0) || (s_cum[a_src][j_src - 1] < x);
    #pragma unroll
    for (int a = 0; a < 6; ++a)
        if (a < a_src && pres[a]) canonical = false;

    unsigned int acc[3] = {0u, 0u, 0u};
    if (canonical && len > 0) {
        // h values at p = x with cross-channel carry.
        int h1 = 0, h2 = 0;
        #pragma unroll
        for (int c = 0; c < 3; ++c) {
            const int c1 = cnt[c], c2 = cnt[c + 3];
            if (c1 <= KBINS - 2)   h1 = c1;
            else if (c1 == KBINS)  h1 = KBINS - 1;   // count was 256
            /* c1 == 255: keep previous channel's value */
            if (c2 <= KBINS - 2)   h2 = c2;
            else if (c2 == KBINS)  h2 = KBINS - 1;
            const int d = h1 - h2;
            // len*d^2 <= 50176*65025 < 2^32; channel totals are sums over
            // disjoint segments tiling [0, NPIX), so they fit u32 too.
            acc[c] = (unsigned int)len * (unsigned int)(d * d);
        }
    }

    // ---- Warp reduce, then warp0 reduces the 6 warp partials. ----
    #pragma unroll
    for (int c = 0; c < 3; ++c)
        acc[c] = __reduce_add_sync(0xFFFFFFFFu, acc[c]);
    if (lane == 0) {
        s_wred[warp][0] = acc[0];
        s_wred[warp][1] = acc[1];
        s_wred[warp][2] = acc[2];
    }
    __syncthreads();

    if (warp == 0 && lane == 0) {
        unsigned int b0 = 0, b1 = 0, b2 = 0;
        #pragma unroll
        for (int w = 0; w < NWARP; ++w) {
            b0 += s_wred[w][0];
            b1 += s_wred[w][1];
            b2 += s_wred[w][2];
        }
        // Channel sums < 2^32 globally: packed u64 adds never carry across
        // the 32-bit field boundary (incl. the count field: NBLK adds of 1).
        atomicAdd(&g_a01, (unsigned long long)b0 |
                          ((unsigned long long)b1 << 32));
        __threadfence();
        const unsigned long long ret =
            atomicAdd(&g_a2c, (1ULL << 32) | (unsigned long long)b2);
        if ((unsigned int)(ret >> 32) == NBLK - 1) {
            // Last block: all peers' g_a01 adds are visible (their fence
            // preceded their g_a2c add, which we just observed).
            __threadfence();
            const unsigned long long a01 = atomicAdd(&g_a01, 0ULL);
            const unsigned int a2 = (unsigned int)(ret & 0xFFFFFFFFu) + b2;
            *out = sqrtf((float)(unsigned int)(a01 & 0xFFFFFFFFu))
                 + sqrtf((float)(unsigned int)(a01 >> 32))
                 + sqrtf((float)a2);
            g_a01 = 0ULL;           // reset for next graph replay
            g_a2c = 0ULL;
            __threadfence();
        }
    }
}

extern "C" void kernel_launch(void* const* d_in, const int* in_sizes, int n_in,
                              void* d_out, int out_size)
{
    const float* target = (const float*)d_in[0];  // (3, 256, 1) fp32
    const float* output = (const float*)d_in[1];  // (3, 256, 1) fp32
    float* out = (float*)d_out;                   // scalar fp32
    (void)in_sizes; (void)n_in; (void)out_size;

    l2hist_kernel<<<NBLK, TPB>>>(target, output, out);
}